// round 11
// baseline (speedup 1.0000x reference)
#include <cuda_runtime.h>
#include <cstdint>

#define NN    8192
#define F_IN  256
#define NHID  128
#define EDGES 524288      // 2^19
#define KTOP  32
#define MAXD  512   // max supported degree per row (mean 64, sigma 8 -> safe)

// ---------------- device scratch (no allocations allowed) ----------------
__device__ float g_a[NN];
__device__ float g_b[NN];
__device__ int   g_count[NN];
__device__ int   g_cursor[NN];
__device__ int   g_start[NN];
__device__ float g_z[EDGES];       // bucket (unsorted within segment)
__device__ int   g_col[EDGES];
__device__ float g_zs[EDGES];      // sorted by (seg, -z)  == ref's zs
__device__ int   g_cols[EDGES];
// ReduceWindowRewriter(base=16) hierarchy: 2^19 -> 32768 -> 2048 -> 128 -> 8
__device__ float g_I1[EDGES];        // inner 16-scans of zs
__device__ float g_s1[EDGES / 16];   // 32768 block sums
__device__ float g_I2[EDGES / 16];   // inner 16-scans of s1
__device__ float g_s2[EDGES / 256];  // 2048
__device__ float g_I3[EDGES / 256];  // inner 16-scans of s2
__device__ float g_s3[EDGES / 4096]; // 128
__device__ float g_O4[EDGES / 4096]; // composed scan of s3 (levels 4+5)

// cs[j] composed on the fly — bit-identical to staged O3/O2 composition:
// O3[k] = (k>>4==0) ? I3[k] : fl(O4[(k>>4)-1] + I3[k])
// O2[i] = (i>>4==0) ? I2[i] : fl(O3[(i>>4)-1] + I2[i])
// cs[j] = (j>>4==0) ? I1[j] : fl(O2[(j>>4)-1] + I1[j])
__device__ __forceinline__ float cs_at(int j) {
    int b1 = j >> 4;
    float v1 = g_I1[j];
    if (b1 == 0) return v1;
    int i1 = b1 - 1;
    int b2 = i1 >> 4;
    float v2 = g_I2[i1];
    float o2;
    if (b2 == 0) {
        o2 = v2;
    } else {
        int i2 = b2 - 1;
        int b3 = i2 >> 4;
        float v3 = g_I3[i2];
        float o3 = (b3 == 0) ? v3 : __fadd_rn(g_O4[b3 - 1], v3);
        o2 = __fadd_rn(o3, v2);
    }
    return __fadd_rn(o2, v1);
}

// sequential ascending 16-fold within half-warp groups via shfl
__device__ __forceinline__ float fold16(float x, int lane) {
    int grp = lane & 16;          // 0 or 16: chunk base within warp
    int l15 = lane & 15;
    float acc = 0.f;
#pragma unroll
    for (int k = 0; k < 16; k++) {
        float v = __shfl_sync(0xffffffffu, x, grp + k);
        if (l15 >= k) acc = (k == 0) ? v : __fadd_rn(acc, v);
    }
    return acc;
}

// ---------------- kernel 1: zero histogram counters ----------------
__global__ void k_zero_counts() {
    int i = blockIdx.x * blockDim.x + threadIdx.x;
    if (i < NN) g_count[i] = 0;
}

// ---------------- kernel 2: h = relu(x @ W1 + b1), fused a/b epilogue ------
// GEMM arithmetic bitwise-identical to reference h (DO NOT TOUCH acc order).
// Epilogue: block owns 64 complete h rows -> per-row sequential ascending FMA
// folds for a = h·We[:128], b = h·We[128:] (identical order to old k_ab).
__global__ void __launch_bounds__(256) k_gemm_relu_ab(
        const float* __restrict__ x,
        const float* __restrict__ W1,
        const float* __restrict__ b1,
        const float* __restrict__ We,
        float* __restrict__ h) {
    __shared__ float xs[64][33];
    __shared__ float ws[32][128];
    __shared__ float hs[64][129];   // padded: conflict-free column reads
    __shared__ float sWe[2 * NHID];
    const int tid = threadIdx.x;
    const int tr = tid >> 5;
    const int tc = tid & 31;
    const int rowBase = blockIdx.x * 64;

    sWe[tid] = We[tid];             // 256 threads load 256 floats

    float acc[8][4];
#pragma unroll
    for (int i = 0; i < 8; i++)
#pragma unroll
        for (int j = 0; j < 4; j++) acc[i][j] = 0.f;

    for (int k0 = 0; k0 < F_IN; k0 += 32) {
#pragma unroll
        for (int l = 0; l < 8; l++) {
            int idx = tid + l * 256;
            int r = idx >> 5;
            int kk = idx & 31;
            xs[r][kk] = x[(size_t)(rowBase + r) * F_IN + k0 + kk];
        }
#pragma unroll
        for (int l = 0; l < 16; l++) {
            int idx = tid + l * 256;
            int kk = idx >> 7;
            int c = idx & 127;
            ws[kk][c] = W1[(size_t)(k0 + kk) * NHID + c];
        }
        __syncthreads();
#pragma unroll
        for (int kk = 0; kk < 32; kk++) {
            float4 b4 = *reinterpret_cast<const float4*>(&ws[kk][tc * 4]);
#pragma unroll
            for (int i = 0; i < 8; i++) {
                float av = xs[tr * 8 + i][kk];
                acc[i][0] += av * b4.x;
                acc[i][1] += av * b4.y;
                acc[i][2] += av * b4.z;
                acc[i][3] += av * b4.w;
            }
        }
        __syncthreads();
    }
#pragma unroll
    for (int i = 0; i < 8; i++) {
        int r = tr * 8 + i;
#pragma unroll
        for (int j = 0; j < 4; j++) {
            int c = tc * 4 + j;
            float v = acc[i][j] + b1[c];
            v = fmaxf(v, 0.f);
            h[(size_t)(rowBase + r) * NHID + c] = v;
            hs[r][c] = v;
        }
    }
    __syncthreads();

    // per-row sequential ascending FMA fold (identical order to old k_ab)
    if (tid < 64) {
        const float* hr = hs[tid];
        float a = 0.f, b = 0.f;
#pragma unroll 16
        for (int i = 0; i < NHID; i++) {
            float hv = hr[i];
            a = __fmaf_rn(hv, sWe[i], a);
            b = __fmaf_rn(hv, sWe[NHID + i], b);
        }
        g_a[rowBase + tid] = a;
        g_b[rowBase + tid] = b;
    }
}

// ---------------- kernel 4: degree histogram ----------------
__global__ void k_hist(const int* __restrict__ rows) {
    int i = blockIdx.x * blockDim.x + threadIdx.x;
    if (i < EDGES) atomicAdd(&g_count[rows[i]], 1);
}

// ---------------- kernel 5: exclusive scan of counts (single block) --------
__global__ void k_scan() {
    __shared__ int sums[1024];
    int tid = threadIdx.x;
    int base = tid * 8;
    int local[8];
    int s = 0;
#pragma unroll
    for (int i = 0; i < 8; i++) { local[i] = s; s += g_count[base + i]; }
    sums[tid] = s;
    __syncthreads();
    for (int off = 1; off < 1024; off <<= 1) {
        int v = (tid >= off) ? sums[tid - off] : 0;
        __syncthreads();
        sums[tid] += v;
        __syncthreads();
    }
    int excl = (tid == 0) ? 0 : sums[tid - 1];
#pragma unroll
    for (int i = 0; i < 8; i++) {
        int st = excl + local[i];
        g_start[base + i] = st;
        g_cursor[base + i] = st;
    }
}

// ---------------- kernel 6: scatter edges into segment buckets -------------
// z replicates reference structure: fl(fl(a + b) + be)
__global__ void k_scatter(const int* __restrict__ ei, const float* __restrict__ be) {
    int j = blockIdx.x * blockDim.x + threadIdx.x;
    if (j >= EDGES) return;
    int r = ei[j];
    int c = ei[EDGES + j];
    int p = atomicAdd(&g_cursor[r], 1);
    g_z[p] = __fadd_rn(__fadd_rn(g_a[r], g_b[c]), be[0]);
    g_col[p] = c;
}

// ---------------- kernel 7: per-row descending sort -> global sorted arrays
__global__ void __launch_bounds__(128) k_rowsort() {
    __shared__ float zr[MAXD];
    __shared__ int   cr[MAXD];
    const int r = blockIdx.x;
    const int tid = threadIdx.x;
    int deg = g_count[r];
    if (deg > MAXD) deg = MAXD;
    if (deg == 0) return;
    const int st = g_start[r];
    for (int i = tid; i < deg; i += 128) {
        zr[i] = g_z[st + i];
        cr[i] = g_col[st + i];
    }
    __syncthreads();
    for (int i = tid; i < deg; i += 128) {
        float zi = zr[i];
        int rk = 0;
        for (int j = 0; j < deg; j++) {
            float zj = zr[j];
            rk += (zj > zi) || (zj == zi && j < i);
        }
        g_zs[st + rk] = zi;
        g_cols[st + rk] = cr[i];
    }
}

// -------- chunk-16 level 1: inner scans of zs + block sums -----------------
__global__ void k16_l1() {
    int j = blockIdx.x * blockDim.x + threadIdx.x;
    float acc = fold16(g_zs[j], threadIdx.x & 31);
    g_I1[j] = acc;
    if ((j & 15) == 15) g_s1[j >> 4] = acc;
}

// -------- level 2: inner scans of s1 (32768) + sums s2 (2048) --------------
__global__ void k16_l2() {
    int j = blockIdx.x * blockDim.x + threadIdx.x;
    float acc = fold16(g_s1[j], threadIdx.x & 31);
    g_I2[j] = acc;
    if ((j & 15) == 15) g_s2[j >> 4] = acc;
}

// -------- levels 3+4+5 fused (single block, 1024 threads) ------------------
// I3 over 2048, s3 (128), I4, O5 (8 native seq), O4 (128)
__global__ void __launch_bounds__(1024) k16_l3top() {
    __shared__ float sI4[128];
    __shared__ float sO5[8];
    int t = threadIdx.x;
#pragma unroll
    for (int p = 0; p < 2; p++) {
        int j = p * 1024 + t;
        float acc = fold16(g_s2[j], t & 31);
        g_I3[j] = acc;
        if ((j & 15) == 15) g_s3[j >> 4] = acc;
    }
    __syncthreads();
    if (t < 128) {
        float acc = fold16(g_s3[t], t & 31);
        sI4[t] = acc;
    }
    __syncthreads();
    if (t == 0) {
        float c = 0.f;
#pragma unroll
        for (int m = 0; m < 8; m++) {
            float s4 = sI4[m * 16 + 15];
            c = (m == 0) ? s4 : __fadd_rn(c, s4);
            sO5[m] = c;
        }
    }
    __syncthreads();
    if (t < 128) {
        int tb = t >> 4;
        g_O4[t] = (tb == 0) ? sI4[t] : __fadd_rn(sO5[tb - 1], sI4[t]);
    }
}

// ---- kernel 10: fused row zero-fill + tau + scores + dedup + topK + write -
// One block per output row (exclusive ownership). Zero the 32 KB row with
// coalesced float4 stores, compute ref-exact tau, then patch sparse cells.
__global__ void __launch_bounds__(256) k_tau_fill(float* __restrict__ adj) {
    __shared__ int   s_kmax;
    __shared__ float s_pref;
    __shared__ int   s_cnt;
    __shared__ float pv[MAXD];
    __shared__ int   pc[MAXD];

    const int r = blockIdx.x;
    const int tid = threadIdx.x;

    // zero-fill this row (268 MB across grid — the HBM-write floor)
    float4* dst = (float4*)(adj + (size_t)r * NN);
    const float4 z4 = make_float4(0.f, 0.f, 0.f, 0.f);
#pragma unroll
    for (int i = 0; i < (NN / 4) / 256; i++) dst[tid + i * 256] = z4;

    int deg = g_count[r];
    if (deg > MAXD) deg = MAXD;
    if (deg == 0) return;          // row stays all-zero (matches reference)
    const int st = g_start[r];

    if (tid == 0) {
        s_kmax = 1;
        // prefix[start] = fl(cs[start] - zs[start])
        s_pref = __fsub_rn(cs_at(st), g_zs[st]);
    }
    __syncthreads();
    const float pref = s_pref;

    // cond = fl(1 + fl((pos+1)*z)) > fl(cs[j] - pref); kmax = max pos+1 true
    int lk = 0;
    for (int i = tid; i < deg; i += 256) {
        float zi = g_zs[st + i];
        float segcs = __fsub_rn(cs_at(st + i), pref);
        float lhs = __fadd_rn(1.0f, __fmul_rn((float)(i + 1), zi));
        if (lhs > segcs) lk = (i + 1) > lk ? (i + 1) : lk;
    }
    if (lk > 0) atomicMax(&s_kmax, lk);
    __syncthreads();

    if (tid == 0) {
        int kmax = s_kmax;
        float sck = __fsub_rn(cs_at(st + kmax - 1), pref);
        float tau = __fdiv_rn(__fsub_rn(sck, 1.0f), (float)kmax);
        // collect distinct positive cells (dup (r,c) -> identical score)
        int cnt = 0;
        for (int i = 0; i < deg; i++) {
            float sc = fmaxf(__fsub_rn(g_zs[st + i], tau), 0.0f);
            if (sc > 0.f) {
                int c = g_cols[st + i];
                bool dup = false;
                for (int j = 0; j < cnt; j++) {
                    if (pc[j] == c) { dup = true; break; }
                }
                if (!dup) { pc[cnt] = c; pv[cnt] = sc; cnt++; }
            }
        }
        s_cnt = cnt;
    }
    __syncthreads();   // also orders the zero stores before the cell patches
    const int cnt = s_cnt;

    // top-K counting rule: keep iff #{cells strictly greater} < KTOP
    for (int i = tid; i < cnt; i += 256) {
        float v = pv[i];
        int ng = 0;
        for (int j = 0; j < cnt; j++) ng += (pv[j] > v);
        if (ng < KTOP) adj[(size_t)r * NN + pc[i]] = v;
    }
}

// ---------------- launcher ----------------
extern "C" void kernel_launch(void* const* d_in, const int* in_sizes, int n_in,
                              void* d_out, int out_size) {
    const float* x  = (const float*)d_in[0];
    const int*   ei = (const int*)d_in[1];
    const float* W1 = (const float*)d_in[2];
    const float* b1 = (const float*)d_in[3];
    const float* We = (const float*)d_in[4];
    const float* be = (const float*)d_in[5];

    float* out = (float*)d_out;
    float* h   = out;                                            // first N*NHID floats
    float* adj = out + ((size_t)out_size - (size_t)NN * NN);     // last N*N floats

    k_zero_counts<<<NN / 256, 256>>>();
    k_gemm_relu_ab<<<NN / 64, 256>>>(x, W1, b1, We, h);
    k_hist<<<EDGES / 256, 256>>>(ei);
    k_scan<<<1, 1024>>>();
    k_scatter<<<EDGES / 256, 256>>>(ei, be);
    k_rowsort<<<NN, 128>>>();
    k16_l1<<<EDGES / 256, 256>>>();
    k16_l2<<<(EDGES / 16) / 256, 256>>>();
    k16_l3top<<<1, 1024>>>();
    k_tau_fill<<<NN, 256>>>(adj);
}

// round 15
// speedup vs baseline: 1.0308x; 1.0308x over previous
#include <cuda_runtime.h>
#include <cstdint>

#define NN    8192
#define F_IN  256
#define NHID  128
#define EDGES 524288      // 2^19
#define KTOP  32
#define MAXD  512   // max supported degree per row (mean 64, sigma 8 -> safe)

// ---------------- device scratch (no allocations allowed) ----------------
__device__ float g_a[NN];
__device__ float g_b[NN];
__device__ int   g_count[NN];
__device__ int   g_cursor[NN];
__device__ int   g_start[NN];
__device__ float g_z[EDGES];       // bucket (unsorted within segment)
__device__ int   g_col[EDGES];
__device__ float g_zs[EDGES];      // sorted by (seg, -z)  == ref's zs
__device__ int   g_cols[EDGES];
// ReduceWindowRewriter(base=16) hierarchy: 2^19 -> 32768 -> 2048 -> 128 -> 8
__device__ float g_I1[EDGES];        // inner 16-scans of zs
__device__ float g_s1[EDGES / 16];   // 32768 block sums
__device__ float g_I2[EDGES / 16];   // inner 16-scans of s1
__device__ float g_s2[EDGES / 256];  // 2048
__device__ float g_I3[EDGES / 256];  // inner 16-scans of s2
__device__ float g_s3[EDGES / 4096]; // 128
__device__ float g_O4[EDGES / 4096]; // composed scan of s3 (levels 4+5)

// cs[j] composed on the fly — bit-identical to staged O3/O2 composition.
__device__ __forceinline__ float cs_at(int j) {
    int b1 = j >> 4;
    float v1 = g_I1[j];
    if (b1 == 0) return v1;
    int i1 = b1 - 1;
    int b2 = i1 >> 4;
    float v2 = g_I2[i1];
    float o2;
    if (b2 == 0) {
        o2 = v2;
    } else {
        int i2 = b2 - 1;
        int b3 = i2 >> 4;
        float v3 = g_I3[i2];
        float o3 = (b3 == 0) ? v3 : __fadd_rn(g_O4[b3 - 1], v3);
        o2 = __fadd_rn(o3, v2);
    }
    return __fadd_rn(o2, v1);
}

// sequential ascending 16-fold within half-warp groups via shfl
__device__ __forceinline__ float fold16(float x, int lane) {
    int grp = lane & 16;
    int l15 = lane & 15;
    float acc = 0.f;
#pragma unroll
    for (int k = 0; k < 16; k++) {
        float v = __shfl_sync(0xffffffffu, x, grp + k);
        if (l15 >= k) acc = (k == 0) ? v : __fadd_rn(acc, v);
    }
    return acc;
}

// ---------------- fill branch: zero the 268 MB adjacency -------------------
__global__ void __launch_bounds__(256) k_fill(float4* __restrict__ adj4) {
    size_t base = (size_t)blockIdx.x * 1024 + threadIdx.x;
    const float4 z4 = make_float4(0.f, 0.f, 0.f, 0.f);
#pragma unroll
    for (int k = 0; k < 4; k++) adj4[base + k * 256] = z4;
}

// ---------------- kernel 1: zero histogram counters ----------------
__global__ void k_zero_counts() {
    int i = blockIdx.x * blockDim.x + threadIdx.x;
    if (i < NN) g_count[i] = 0;
}

// ---------------- kernel 2: h = relu(x @ W1 + b1), fused a/b epilogue ------
// GEMM arithmetic bitwise-identical to reference h (DO NOT TOUCH acc order).
__global__ void __launch_bounds__(256) k_gemm_relu_ab(
        const float* __restrict__ x,
        const float* __restrict__ W1,
        const float* __restrict__ b1,
        const float* __restrict__ We,
        float* __restrict__ h) {
    __shared__ float xs[64][33];
    __shared__ float ws[32][128];
    __shared__ float hs[64][129];   // padded: conflict-free column reads
    __shared__ float sWe[2 * NHID];
    const int tid = threadIdx.x;
    const int tr = tid >> 5;
    const int tc = tid & 31;
    const int rowBase = blockIdx.x * 64;

    sWe[tid] = We[tid];

    float acc[8][4];
#pragma unroll
    for (int i = 0; i < 8; i++)
#pragma unroll
        for (int j = 0; j < 4; j++) acc[i][j] = 0.f;

    for (int k0 = 0; k0 < F_IN; k0 += 32) {
#pragma unroll
        for (int l = 0; l < 8; l++) {
            int idx = tid + l * 256;
            int r = idx >> 5;
            int kk = idx & 31;
            xs[r][kk] = x[(size_t)(rowBase + r) * F_IN + k0 + kk];
        }
#pragma unroll
        for (int l = 0; l < 16; l++) {
            int idx = tid + l * 256;
            int kk = idx >> 7;
            int c = idx & 127;
            ws[kk][c] = W1[(size_t)(k0 + kk) * NHID + c];
        }
        __syncthreads();
#pragma unroll
        for (int kk = 0; kk < 32; kk++) {
            float4 b4 = *reinterpret_cast<const float4*>(&ws[kk][tc * 4]);
#pragma unroll
            for (int i = 0; i < 8; i++) {
                float av = xs[tr * 8 + i][kk];
                acc[i][0] += av * b4.x;
                acc[i][1] += av * b4.y;
                acc[i][2] += av * b4.z;
                acc[i][3] += av * b4.w;
            }
        }
        __syncthreads();
    }
#pragma unroll
    for (int i = 0; i < 8; i++) {
        int r = tr * 8 + i;
#pragma unroll
        for (int j = 0; j < 4; j++) {
            int c = tc * 4 + j;
            float v = acc[i][j] + b1[c];
            v = fmaxf(v, 0.f);
            h[(size_t)(rowBase + r) * NHID + c] = v;
            hs[r][c] = v;
        }
    }
    __syncthreads();

    // per-row sequential ascending FMA fold (identical order to old k_ab)
    if (tid < 64) {
        const float* hr = hs[tid];
        float a = 0.f, b = 0.f;
#pragma unroll 16
        for (int i = 0; i < NHID; i++) {
            float hv = hr[i];
            a = __fmaf_rn(hv, sWe[i], a);
            b = __fmaf_rn(hv, sWe[NHID + i], b);
        }
        g_a[rowBase + tid] = a;
        g_b[rowBase + tid] = b;
    }
}

// ---------------- kernel 4: degree histogram ----------------
__global__ void k_hist(const int* __restrict__ rows) {
    int i = blockIdx.x * blockDim.x + threadIdx.x;
    if (i < EDGES) atomicAdd(&g_count[rows[i]], 1);
}

// ---------------- kernel 5: fast exclusive scan of counts (1 block, shfl) --
__global__ void __launch_bounds__(256) k_scan() {
    __shared__ int wsum[8];
    __shared__ int wexcl[8];
    const int tid = threadIdx.x;
    const int lane = tid & 31, wid = tid >> 5;
    const int base = tid * 32;
    int s = 0;
#pragma unroll
    for (int i = 0; i < 32; i++) s += g_count[base + i];
    int inc = s;
#pragma unroll
    for (int o = 1; o < 32; o <<= 1) {
        int v = __shfl_up_sync(0xffffffffu, inc, o);
        if (lane >= o) inc += v;
    }
    if (lane == 31) wsum[wid] = inc;
    __syncthreads();
    if (tid == 0) {
        int acc = 0;
#pragma unroll
        for (int w = 0; w < 8; w++) { wexcl[w] = acc; acc += wsum[w]; }
    }
    __syncthreads();
    int running = wexcl[wid] + inc - s;
#pragma unroll
    for (int i = 0; i < 32; i++) {
        g_start[base + i] = running;
        g_cursor[base + i] = running;
        running += g_count[base + i];
    }
}

// ---------------- kernel 6: scatter edges into segment buckets -------------
// z replicates reference structure: fl(fl(a + b) + be)
__global__ void k_scatter(const int* __restrict__ ei, const float* __restrict__ be) {
    int j = blockIdx.x * blockDim.x + threadIdx.x;
    if (j >= EDGES) return;
    int r = ei[j];
    int c = ei[EDGES + j];
    int p = atomicAdd(&g_cursor[r], 1);
    g_z[p] = __fadd_rn(__fadd_rn(g_a[r], g_b[c]), be[0]);
    g_col[p] = c;
}

// ---------------- kernel 7: per-row descending sort -> global sorted arrays
__global__ void __launch_bounds__(128) k_rowsort() {
    __shared__ float zr[MAXD];
    __shared__ int   cr[MAXD];
    const int r = blockIdx.x;
    const int tid = threadIdx.x;
    int deg = g_count[r];
    if (deg > MAXD) deg = MAXD;
    if (deg == 0) return;
    const int st = g_start[r];
    for (int i = tid; i < deg; i += 128) {
        zr[i] = g_z[st + i];
        cr[i] = g_col[st + i];
    }
    __syncthreads();
    for (int i = tid; i < deg; i += 128) {
        float zi = zr[i];
        int rk = 0;
        for (int j = 0; j < deg; j++) {
            float zj = zr[j];
            rk += (zj > zi) || (zj == zi && j < i);
        }
        g_zs[st + rk] = zi;
        g_cols[st + rk] = cr[i];
    }
}

// -------- chunk-16 level 1: inner scans of zs + block sums -----------------
__global__ void k16_l1() {
    int j = blockIdx.x * blockDim.x + threadIdx.x;
    float acc = fold16(g_zs[j], threadIdx.x & 31);
    g_I1[j] = acc;
    if ((j & 15) == 15) g_s1[j >> 4] = acc;
}

// -------- level 2: inner scans of s1 (32768) + sums s2 (2048) --------------
__global__ void k16_l2() {
    int j = blockIdx.x * blockDim.x + threadIdx.x;
    float acc = fold16(g_s1[j], threadIdx.x & 31);
    g_I2[j] = acc;
    if ((j & 15) == 15) g_s2[j >> 4] = acc;
}

// -------- levels 3+4+5 fused (single block, 1024 threads) ------------------
__global__ void __launch_bounds__(1024) k16_l3top() {
    __shared__ float sI4[128];
    __shared__ float sO5[8];
    int t = threadIdx.x;
#pragma unroll
    for (int p = 0; p < 2; p++) {
        int j = p * 1024 + t;
        float acc = fold16(g_s2[j], t & 31);
        g_I3[j] = acc;
        if ((j & 15) == 15) g_s3[j >> 4] = acc;
    }
    __syncthreads();
    if (t < 128) {
        float acc = fold16(g_s3[t], t & 31);
        sI4[t] = acc;
    }
    __syncthreads();
    if (t == 0) {
        float c = 0.f;
#pragma unroll
        for (int m = 0; m < 8; m++) {
            float s4 = sI4[m * 16 + 15];
            c = (m == 0) ? s4 : __fadd_rn(c, s4);
            sO5[m] = c;
        }
    }
    __syncthreads();
    if (t < 128) {
        int tb = t >> 4;
        g_O4[t] = (tb == 0) ? sI4[t] : __fadd_rn(sO5[tb - 1], sI4[t]);
    }
}

// ---- kernel 10: tau + scores + dedup + topK + sparse patch (no fill) ------
__global__ void __launch_bounds__(128) k_tau(float* __restrict__ adj) {
    __shared__ int   s_kmax;
    __shared__ float s_pref;
    __shared__ int   s_cnt;
    __shared__ float pv[MAXD];
    __shared__ int   pc[MAXD];

    const int r = blockIdx.x;
    const int tid = threadIdx.x;
    int deg = g_count[r];
    if (deg > MAXD) deg = MAXD;
    if (deg == 0) return;          // row stays all-zero (matches reference)
    const int st = g_start[r];

    if (tid == 0) {
        s_kmax = 1;
        // prefix[start] = fl(cs[start] - zs[start])
        s_pref = __fsub_rn(cs_at(st), g_zs[st]);
    }
    __syncthreads();
    const float pref = s_pref;

    // cond = fl(1 + fl((pos+1)*z)) > fl(cs[j] - pref); kmax = max pos+1 true
    int lk = 0;
    for (int i = tid; i < deg; i += 128) {
        float zi = g_zs[st + i];
        float segcs = __fsub_rn(cs_at(st + i), pref);
        float lhs = __fadd_rn(1.0f, __fmul_rn((float)(i + 1), zi));
        if (lhs > segcs) lk = (i + 1) > lk ? (i + 1) : lk;
    }
    if (lk > 0) atomicMax(&s_kmax, lk);
    __syncthreads();

    if (tid == 0) {
        int kmax = s_kmax;
        float sck = __fsub_rn(cs_at(st + kmax - 1), pref);
        float tau = __fdiv_rn(__fsub_rn(sck, 1.0f), (float)kmax);
        // collect distinct positive cells (dup (r,c) -> identical score)
        int cnt = 0;
        for (int i = 0; i < deg; i++) {
            float sc = fmaxf(__fsub_rn(g_zs[st + i], tau), 0.0f);
            if (sc > 0.f) {
                int c = g_cols[st + i];
                bool dup = false;
                for (int j = 0; j < cnt; j++) {
                    if (pc[j] == c) { dup = true; break; }
                }
                if (!dup) { pc[cnt] = c; pv[cnt] = sc; cnt++; }
            }
        }
        s_cnt = cnt;
    }
    __syncthreads();
    const int cnt = s_cnt;

    // top-K counting rule: keep iff #{cells strictly greater} < KTOP
    for (int i = tid; i < cnt; i += 128) {
        float v = pv[i];
        int ng = 0;
        for (int j = 0; j < cnt; j++) ng += (pv[j] > v);
        if (ng < KTOP) adj[(size_t)r * NN + pc[i]] = v;
    }
}

// ---------------- launcher: fork fill onto a side stream -------------------
extern "C" void kernel_launch(void* const* d_in, const int* in_sizes, int n_in,
                              void* d_out, int out_size) {
    const float* x  = (const float*)d_in[0];
    const int*   ei = (const int*)d_in[1];
    const float* W1 = (const float*)d_in[2];
    const float* b1 = (const float*)d_in[3];
    const float* We = (const float*)d_in[4];
    const float* be = (const float*)d_in[5];

    float* out = (float*)d_out;
    float* h   = out;                                            // first N*NHID floats
    float* adj = out + ((size_t)out_size - (size_t)NN * NN);     // last N*N floats

    // fork: fill branch runs concurrently with the edge pipeline.
    // (host-API stream/event creation is capture-safe; no device allocations)
    cudaStream_t s2;
    cudaStreamCreateWithFlags(&s2, cudaStreamNonBlocking);
    cudaEvent_t evFork, evJoin;
    cudaEventCreateWithFlags(&evFork, cudaEventDisableTiming);
    cudaEventCreateWithFlags(&evJoin, cudaEventDisableTiming);

    cudaEventRecord(evFork, 0);
    cudaStreamWaitEvent(s2, evFork, 0);
    k_fill<<<(NN * (size_t)NN / 4) / 1024, 256, 0, s2>>>((float4*)adj);
    cudaEventRecord(evJoin, s2);

    // main pipeline (default stream)
    k_zero_counts<<<NN / 256, 256>>>();
    k_gemm_relu_ab<<<NN / 64, 256>>>(x, W1, b1, We, h);
    k_hist<<<EDGES / 256, 256>>>(ei);
    k_scan<<<1, 256>>>();
    k_scatter<<<EDGES / 256, 256>>>(ei, be);
    k_rowsort<<<NN, 128>>>();
    k16_l1<<<EDGES / 256, 256>>>();
    k16_l2<<<(EDGES / 16) / 256, 256>>>();
    k16_l3top<<<1, 1024>>>();

    // join: patch must see the zero-filled adjacency
    cudaStreamWaitEvent(0, evJoin, 0);
    k_tau<<<NN, 128>>>(adj);
}